// round 11
// baseline (speedup 1.0000x reference)
#include <cuda_runtime.h>
#include <cstdint>

#define T_STEPS 8192
#define H_DIM 256
#define E_DIM 256
#define G_DIM 1024   // 4*H
#define CL 8         // cluster size

// 32 MB scratch for xg = emb@W_ih^T + bias  (allocation-free rule: device global)
__device__ float g_xg[(size_t)T_STEPS * G_DIM];

// ---------------------------------------------------------------------------
// helpers
// ---------------------------------------------------------------------------
__device__ __forceinline__ uint32_t smem_u32(const void* p) {
    uint32_t a;
    asm("{ .reg .u64 t; cvta.to.shared.u64 t, %1; cvt.u32.u64 %0, t; }"
        : "=r"(a) : "l"(p));
    return a;
}

__device__ __forceinline__ void ffma2(unsigned long long& d,
                                      unsigned long long a,
                                      unsigned long long b) {
    asm("fma.rn.f32x2 %0, %1, %2, %0;" : "+l"(d) : "l"(a), "l"(b));
}

__device__ __forceinline__ float lo32(unsigned long long v) {
    return __uint_as_float((uint32_t)v);
}
__device__ __forceinline__ float hi32(unsigned long long v) {
    return __uint_as_float((uint32_t)(v >> 32));
}

__device__ __forceinline__ float tanh_fast(float x) {
    float r;
    asm("tanh.approx.f32 %0, %1;" : "=f"(r) : "f"(x));
    return r;
}
// sigmoid(x) = 0.5*tanh(0.5x) + 0.5   (MUFU tanh, no div)
__device__ __forceinline__ float sigmoid_fast(float x) {
    return fmaf(0.5f, tanh_fast(0.5f * x), 0.5f);
}

__device__ __forceinline__ void mbar_wait(uint32_t addr, uint32_t parity) {
    uint32_t done;
    asm volatile(
        "{\n\t.reg .pred p;\n\t"
        "mbarrier.try_wait.parity.acquire.cta.shared::cta.b64 p, [%1], %2;\n\t"
        "selp.b32 %0, 1, 0, p;\n\t}"
        : "=r"(done) : "r"(addr), "r"(parity) : "memory");
    if (!done) {
        asm volatile(
            "{\n\t.reg .pred P1;\n"
            "WL_%=:\n\t"
            "mbarrier.try_wait.parity.acquire.cta.shared::cta.b64 P1, [%0], %1, 0x989680;\n\t"
            "@P1 bra.uni WD_%=;\n\t"
            "bra.uni WL_%=;\n"
            "WD_%=:\n\t}"
            :: "r"(addr), "r"(parity) : "memory");
    }
}

// ---------------------------------------------------------------------------
// Kernel A: xg[t][r] = sum_k emb[tokens[t]][k] * W_ih[r][k] + (b_ih[r]+b_hh[r])
// ---------------------------------------------------------------------------
__global__ __launch_bounds__(256) void xg_gemm(const int* __restrict__ tokens,
                                               const float* __restrict__ emb,
                                               const float* __restrict__ Wih,
                                               const float* __restrict__ bih,
                                               const float* __restrict__ bhh) {
    __shared__ __align__(16) float As[32][132];
    __shared__ __align__(16) float Bs[32][132];
    __shared__ int stok[128];

    const int tid = threadIdx.x;
    const int t0 = blockIdx.y * 128;
    const int r0 = blockIdx.x * 128;

    if (tid < 128) stok[tid] = tokens[t0 + tid];
    __syncthreads();

    const int ty = tid >> 4;
    const int tx = tid & 15;

    float acc[8][8];
#pragma unroll
    for (int i = 0; i < 8; i++)
#pragma unroll
        for (int j = 0; j < 8; j++) acc[i][j] = 0.0f;

    for (int k0 = 0; k0 < E_DIM; k0 += 32) {
#pragma unroll
        for (int q = 0; q < 4; q++) {
            int v = q * 256 + tid;
            int row = v >> 3;
            int c4 = v & 7;
            float4 a = *(const float4*)(emb + (size_t)stok[row] * E_DIM + k0 + c4 * 4);
            As[c4 * 4 + 0][row] = a.x; As[c4 * 4 + 1][row] = a.y;
            As[c4 * 4 + 2][row] = a.z; As[c4 * 4 + 3][row] = a.w;
            float4 b = *(const float4*)(Wih + (size_t)(r0 + row) * E_DIM + k0 + c4 * 4);
            Bs[c4 * 4 + 0][row] = b.x; Bs[c4 * 4 + 1][row] = b.y;
            Bs[c4 * 4 + 2][row] = b.z; Bs[c4 * 4 + 3][row] = b.w;
        }
        __syncthreads();

#pragma unroll
        for (int k = 0; k < 32; k++) {
            float a[8], b[8];
            float4 a0 = *(const float4*)&As[k][ty * 8];
            float4 a1 = *(const float4*)&As[k][ty * 8 + 4];
            float4 b0 = *(const float4*)&Bs[k][tx * 8];
            float4 b1 = *(const float4*)&Bs[k][tx * 8 + 4];
            a[0]=a0.x; a[1]=a0.y; a[2]=a0.z; a[3]=a0.w;
            a[4]=a1.x; a[5]=a1.y; a[6]=a1.z; a[7]=a1.w;
            b[0]=b0.x; b[1]=b0.y; b[2]=b0.z; b[3]=b0.w;
            b[4]=b1.x; b[5]=b1.y; b[6]=b1.z; b[7]=b1.w;
#pragma unroll
            for (int i = 0; i < 8; i++)
#pragma unroll
                for (int j = 0; j < 8; j++)
                    acc[i][j] = fmaf(a[i], b[j], acc[i][j]);
        }
        __syncthreads();
    }

#pragma unroll
    for (int j = 0; j < 8; j++) {
        int r = r0 + tx * 8 + j;
        float bias = bih[r] + bhh[r];
#pragma unroll
        for (int i = 0; i < 8; i++) {
            g_xg[(size_t)(t0 + ty * 8 + i) * G_DIM + r] = acc[i][j] + bias;
        }
    }
}

// ---------------------------------------------------------------------------
// Kernel B: persistent 8-CTA cluster LSTM scan —
//   single-phase compute + per-source barriers + v4 st.async packets.
//
//   Warp w owns elems 4w..4w+3 (global E = 32*rank + 4w + (l&3)).
//   Lane l: eidx = l&3, K-slice s = l>>2 (8 slices x 32 floats).
//   Consumer side: warp w reads slice [32w,32w+32) = source CTA w's elems,
//   so warp w waits ONLY bars[w][t&1] (parity ((t-1)>>1)&1) and lane 0
//   re-arms it (expect_tx=128B) for step t+2 BEFORE this warp's own push.
//   Producer side: after reduce + activations (lanes 0-3, MUFU tanh),
//   all lanes shfl the 4 hv values; lanes 0-7 send ONE 16B
//   st.async.v4.b32 packet to dest CTA l (slot rank*32+4w), completing on
//   dest bars[rank][(t+1)&1]. 8 msgs per (src,dst) pair per step.
//
//   Safety (arm-before-tx): source w's sends for t+2 require its h(t+1)
//   wait, which requires OUR warp-w push of h(t+1), which follows our
//   warp-w arm at step t. hbuf parity double-buffer safe as before.
// ---------------------------------------------------------------------------
__global__ __launch_bounds__(256, 1) __cluster_dims__(CL, 1, 1)
void lstm_scan(const float* __restrict__ Whh, float* __restrict__ out) {
    __shared__ __align__(16) float hbuf[2][H_DIM];
    __shared__ __align__(8) unsigned long long bars[CL][2];   // [source][parity]

    const uint32_t smem_h = smem_u32(&hbuf[0][0]);
    const uint32_t smem_bars = smem_u32(&bars[0][0]);

    const int tid = threadIdx.x;
    const int w = tid >> 5;
    const int l = tid & 31;
    const int eidx = l & 3;
    const int s = l >> 2;
    uint32_t rank;
    asm("mov.u32 %0, %%cluster_ctarank;" : "=r"(rank));

    const int E = (int)rank * 32 + 4 * w + eidx;   // global h element

    // weights: 4 gate rows of element E, K slice [32s, 32s+32), packed f32x2.
    unsigned long long wt[4][16];
#pragma unroll
    for (int g = 0; g < 4; g++) {
        const unsigned long long* wr =
            (const unsigned long long*)(Whh + (size_t)(g * H_DIM + E) * H_DIM + 32 * s);
#pragma unroll
        for (int i = 0; i < 16; i++) wt[g][i] = wr[i];
    }

    // init
    for (int i = tid; i < 2 * H_DIM; i += 256) ((float*)hbuf)[i] = 0.0f;
    if (tid < 2 * CL) {
        asm volatile("mbarrier.init.shared.b64 [%0], %1;"
                     :: "r"(smem_bars + (uint32_t)tid * 8), "r"(1) : "memory");
    }
    __syncthreads();
    // pre-arm bars[w][1] for t=1 (one arm per source barrier, by warp w lane 0)
    if (l == 0) {
        asm volatile("mbarrier.arrive.expect_tx.shared.b64 _, [%0], %1;"
                     :: "r"(smem_bars + (uint32_t)(w * 2 + 1) * 8), "r"(128)
                     : "memory");
    }
    __syncthreads();
    asm volatile("barrier.cluster.arrive.aligned;" ::: "memory");
    asm volatile("barrier.cluster.wait.aligned;" ::: "memory");

    // push lanes (0-7): dest CTA = l. One v4.b32 packet: elems 4w..4w+3.
    uint32_t dsth = 0, dstb = 0;
    if (l < CL) {
        uint32_t hoff = smem_h + (uint32_t)(rank * 32 + 4 * w) * 4;
        uint32_t boff = smem_bars + rank * 16;   // bars[rank][0]
        asm("mapa.shared::cluster.u32 %0, %1, %2;"
            : "=r"(dsth) : "r"(hoff), "r"(l));
        asm("mapa.shared::cluster.u32 %0, %1, %2;"
            : "=r"(dstb) : "r"(boff), "r"(l));
    }

    float c = 0.0f;
    float xn0 = 0.f, xn1 = 0.f, xn2 = 0.f, xn3 = 0.f;
    if (l < 4) {
        xn0 = g_xg[0 * H_DIM + E];
        xn1 = g_xg[1 * H_DIM + E];
        xn2 = g_xg[2 * H_DIM + E];
        xn3 = g_xg[3 * H_DIM + E];
    }

    const uint32_t mybar0 = smem_bars + (uint32_t)(w * 2) * 8;

    for (int t = 0; t < T_STEPS; t++) {
        const uint32_t mybar = mybar0 + (uint32_t)(t & 1) * 8;
        // ---- wait ONLY this warp's source barrier, then re-arm for t+2 ----
        if (t > 0) mbar_wait(mybar, (uint32_t)(((t - 1) >> 1) & 1));
        if (l == 0) {
            asm volatile("mbarrier.arrive.expect_tx.shared.b64 _, [%0], %1;"
                         :: "r"(mybar), "r"(128) : "memory");
        }

        // ---- full dots: slice [32s,32s+32) of h ----
        const ulonglong2* hp =
            (const ulonglong2*)((const char*)hbuf + (t & 1) * (H_DIM * 4) + s * 128);
        unsigned long long hh[16];
#pragma unroll
        for (int i = 0; i < 8; i++) {
            ulonglong2 q = hp[i];
            hh[2 * i + 0] = q.x;
            hh[2 * i + 1] = q.y;
        }
        unsigned long long a0 = 0ull, a1 = 0ull, a2 = 0ull, a3 = 0ull;
#pragma unroll
        for (int j = 0; j < 16; j++) {
            ffma2(a0, wt[0][j], hh[j]);
            ffma2(a1, wt[1][j], hh[j]);
            ffma2(a2, wt[2][j], hh[j]);
            ffma2(a3, wt[3][j], hh[j]);
        }
        float si = lo32(a0) + hi32(a0);
        float sf = lo32(a1) + hi32(a1);
        float sg = lo32(a2) + hi32(a2);
        float so = lo32(a3) + hi32(a3);

        // reduce across 8 K-slices (lane bits 2,3,4)
#pragma unroll
        for (int off = 4; off <= 16; off <<= 1) {
            si += __shfl_xor_sync(0xFFFFFFFFu, si, off);
            sf += __shfl_xor_sync(0xFFFFFFFFu, sf, off);
            sg += __shfl_xor_sync(0xFFFFFFFFu, sg, off);
            so += __shfl_xor_sync(0xFFFFFFFFu, so, off);
        }

        // ---- activations (lanes 0-3; c in-lane), MUFU tanh.approx ----
        float hv = 0.0f;
        if (l < 4) {
            float iv = sigmoid_fast(si + xn0);
            float fv = sigmoid_fast(sf + xn1);
            float gv = tanh_fast(sg + xn2);
            float ov = sigmoid_fast(so + xn3);
            c = fv * c + iv * gv;
            hv = ov * tanh_fast(c);
        }

        // ---- pack 4 elems + push one v4 packet per dest (lanes 0-7) ----
        if (t < T_STEPS - 1) {
            uint32_t u0 = __shfl_sync(0xFFFFFFFFu, __float_as_uint(hv), 0);
            uint32_t u1 = __shfl_sync(0xFFFFFFFFu, __float_as_uint(hv), 1);
            uint32_t u2 = __shfl_sync(0xFFFFFFFFu, __float_as_uint(hv), 2);
            uint32_t u3 = __shfl_sync(0xFFFFFFFFu, __float_as_uint(hv), 3);
            if (l < CL) {
                const uint32_t hoff = (uint32_t)((t + 1) & 1) * (H_DIM * 4);
                const uint32_t boff = (uint32_t)((t + 1) & 1) * 8;
                asm volatile(
                    "st.async.shared::cluster.mbarrier::complete_tx::bytes.v4.b32 "
                    "[%0], {%1,%2,%3,%4}, [%5];"
                    :: "r"(dsth + hoff), "r"(u0), "r"(u1), "r"(u2), "r"(u3),
                       "r"(dstb + boff)
                    : "memory");
            }
        }

        // ---- off critical path: output + next xg prefetch ----
        if (l < 4) {
            out[(size_t)t * H_DIM + E] = hv;
            if (t == T_STEPS - 1) {
                out[(size_t)T_STEPS * H_DIM + E] = hv;
                out[(size_t)T_STEPS * H_DIM + H_DIM + E] = c;
            }
            int tn = (t + 1 < T_STEPS) ? (t + 1) : t;
            const float* xr = g_xg + (size_t)tn * G_DIM + E;
            xn0 = xr[0]; xn1 = xr[256]; xn2 = xr[512]; xn3 = xr[768];
        }
    }
}

// ---------------------------------------------------------------------------
extern "C" void kernel_launch(void* const* d_in, const int* in_sizes, int n_in,
                              void* d_out, int out_size) {
    const int* tokens = (const int*)d_in[0];
    const float* emb = (const float*)d_in[1];
    const float* Wih = (const float*)d_in[2];
    const float* Whh = (const float*)d_in[3];
    const float* bih = (const float*)d_in[4];
    const float* bhh = (const float*)d_in[5];
    float* out = (float*)d_out;

    dim3 gA(8, 64);
    xg_gemm<<<gA, 256>>>(tokens, emb, Wih, bih, bhh);
    lstm_scan<<<CL, 256>>>(Whh, out);
}

// round 12
// speedup vs baseline: 1.1310x; 1.1310x over previous
#include <cuda_runtime.h>
#include <cstdint>

#define T_STEPS 8192
#define H_DIM 256
#define E_DIM 256
#define G_DIM 1024   // 4*H
#define CL 8         // cluster size

// 32 MB scratch for xg = emb@W_ih^T + bias  (allocation-free rule: device global)
__device__ float g_xg[(size_t)T_STEPS * G_DIM];

// ---------------------------------------------------------------------------
// helpers
// ---------------------------------------------------------------------------
__device__ __forceinline__ uint32_t smem_u32(const void* p) {
    uint32_t a;
    asm("{ .reg .u64 t; cvta.to.shared.u64 t, %1; cvt.u32.u64 %0, t; }"
        : "=r"(a) : "l"(p));
    return a;
}

__device__ __forceinline__ void ffma2(unsigned long long& d,
                                      unsigned long long a,
                                      unsigned long long b) {
    asm("fma.rn.f32x2 %0, %1, %2, %0;" : "+l"(d) : "l"(a), "l"(b));
}
__device__ __forceinline__ void fadd2(unsigned long long& d,
                                      unsigned long long a) {
    asm("add.rn.f32x2 %0, %0, %1;" : "+l"(d) : "l"(a));
}

__device__ __forceinline__ float lo32(unsigned long long v) {
    return __uint_as_float((uint32_t)v);
}
__device__ __forceinline__ float hi32(unsigned long long v) {
    return __uint_as_float((uint32_t)(v >> 32));
}

__device__ __forceinline__ float tanh_fast(float x) {
    float r;
    asm("tanh.approx.f32 %0, %1;" : "=f"(r) : "f"(x));
    return r;
}
// sigmoid(x) = 0.5*tanh(0.5x) + 0.5   (MUFU tanh, no div)
__device__ __forceinline__ float sigmoid_fast(float x) {
    return fmaf(0.5f, tanh_fast(0.5f * x), 0.5f);
}

__device__ __forceinline__ void mbar_wait(uint32_t addr, uint32_t parity) {
    uint32_t done;
    asm volatile(
        "{\n\t.reg .pred p;\n\t"
        "mbarrier.try_wait.parity.acquire.cta.shared::cta.b64 p, [%1], %2;\n\t"
        "selp.b32 %0, 1, 0, p;\n\t}"
        : "=r"(done) : "r"(addr), "r"(parity) : "memory");
    if (!done) {
        asm volatile(
            "{\n\t.reg .pred P1;\n"
            "WL_%=:\n\t"
            "mbarrier.try_wait.parity.acquire.cta.shared::cta.b64 P1, [%0], %1, 0x989680;\n\t"
            "@P1 bra.uni WD_%=;\n\t"
            "bra.uni WL_%=;\n"
            "WD_%=:\n\t}"
            :: "r"(addr), "r"(parity) : "memory");
    }
}

// ---------------------------------------------------------------------------
// Kernel A: xg[t][r] = sum_k emb[tokens[t]][k] * W_ih[r][k] + (b_ih[r]+b_hh[r])
// ---------------------------------------------------------------------------
__global__ __launch_bounds__(256) void xg_gemm(const int* __restrict__ tokens,
                                               const float* __restrict__ emb,
                                               const float* __restrict__ Wih,
                                               const float* __restrict__ bih,
                                               const float* __restrict__ bhh) {
    __shared__ __align__(16) float As[32][132];
    __shared__ __align__(16) float Bs[32][132];
    __shared__ int stok[128];

    const int tid = threadIdx.x;
    const int t0 = blockIdx.y * 128;
    const int r0 = blockIdx.x * 128;

    if (tid < 128) stok[tid] = tokens[t0 + tid];
    __syncthreads();

    const int ty = tid >> 4;
    const int tx = tid & 15;

    float acc[8][8];
#pragma unroll
    for (int i = 0; i < 8; i++)
#pragma unroll
        for (int j = 0; j < 8; j++) acc[i][j] = 0.0f;

    for (int k0 = 0; k0 < E_DIM; k0 += 32) {
#pragma unroll
        for (int q = 0; q < 4; q++) {
            int v = q * 256 + tid;
            int row = v >> 3;
            int c4 = v & 7;
            float4 a = *(const float4*)(emb + (size_t)stok[row] * E_DIM + k0 + c4 * 4);
            As[c4 * 4 + 0][row] = a.x; As[c4 * 4 + 1][row] = a.y;
            As[c4 * 4 + 2][row] = a.z; As[c4 * 4 + 3][row] = a.w;
            float4 b = *(const float4*)(Wih + (size_t)(r0 + row) * E_DIM + k0 + c4 * 4);
            Bs[c4 * 4 + 0][row] = b.x; Bs[c4 * 4 + 1][row] = b.y;
            Bs[c4 * 4 + 2][row] = b.z; Bs[c4 * 4 + 3][row] = b.w;
        }
        __syncthreads();

#pragma unroll
        for (int k = 0; k < 32; k++) {
            float a[8], b[8];
            float4 a0 = *(const float4*)&As[k][ty * 8];
            float4 a1 = *(const float4*)&As[k][ty * 8 + 4];
            float4 b0 = *(const float4*)&Bs[k][tx * 8];
            float4 b1 = *(const float4*)&Bs[k][tx * 8 + 4];
            a[0]=a0.x; a[1]=a0.y; a[2]=a0.z; a[3]=a0.w;
            a[4]=a1.x; a[5]=a1.y; a[6]=a1.z; a[7]=a1.w;
            b[0]=b0.x; b[1]=b0.y; b[2]=b0.z; b[3]=b0.w;
            b[4]=b1.x; b[5]=b1.y; b[6]=b1.z; b[7]=b1.w;
#pragma unroll
            for (int i = 0; i < 8; i++)
#pragma unroll
                for (int j = 0; j < 8; j++)
                    acc[i][j] = fmaf(a[i], b[j], acc[i][j]);
        }
        __syncthreads();
    }

#pragma unroll
    for (int j = 0; j < 8; j++) {
        int r = r0 + tx * 8 + j;
        float bias = bih[r] + bhh[r];
#pragma unroll
        for (int i = 0; i < 8; i++) {
            g_xg[(size_t)(t0 + ty * 8 + i) * G_DIM + r] = acc[i][j] + bias;
        }
    }
}

// ---------------------------------------------------------------------------
// Kernel B: persistent 8-CTA cluster LSTM scan — st.async handoff (R9 base).
//   Two-phase, per-source barriers (wait matches read slice), v4 packets,
//   MUFU tanh activations.
//
//   Barriers: bars[source][parity], count=1, expect_tx=128B per phase
//   (8 x v4.b32 packets from that source). Consumer warp w waits only
//   bars[w][t&1] at parity ((t-1)>>1)&1, then lane 0 re-arms it for t+2.
//   Pre-loop arms bars[w][1] for t=1.
//   Arm-before-tx safety (as R9): any source's t+2 sends require its
//   syncthreads(t+1), which requires its warp_rank's wait of OUR h(t+1)
//   push (warp 0, after OUR syncthreads(t)), which follows ALL our warps'
//   arms at step t.
//
//   Phase 1: warp w, lane e: 4 gate partial dots of elem e over slice
//            [32w,32w+32); STS into part[t&1][w][e][4].
//   Phase 2 (after __syncthreads): warp 0 lane e: reduce 8 partials,
//            MUFU activations (c in-lane); all 32 lanes gather hv via shfl
//            and push 2 v4 packets each (lane l: packets l>>3 and
//            (l>>3)+4, dest l&7). out/xg off critical path.
// ---------------------------------------------------------------------------
__global__ __launch_bounds__(256, 1) __cluster_dims__(CL, 1, 1)
void lstm_scan(const float* __restrict__ Whh, float* __restrict__ out) {
    __shared__ __align__(16) float hbuf[2][H_DIM];
    __shared__ __align__(16) float part[2][8][32][4];
    __shared__ __align__(8) unsigned long long bars[CL][2];

    const uint32_t smem_h = smem_u32(&hbuf[0][0]);
    const uint32_t smem_bars = smem_u32(&bars[0][0]);

    const int tid = threadIdx.x;
    const int w = tid >> 5;    // warp = K-slice = source CTA index
    const int e = tid & 31;    // element within CTA's 32
    uint32_t rank;
    asm("mov.u32 %0, %%cluster_ctarank;" : "=r"(rank));

    const int E = (int)rank * 32 + e;   // global h element

    // weights: 4 gate rows of element E, K slice [32w, 32w+32), packed f32x2.
    unsigned long long wt[4][16];
#pragma unroll
    for (int g = 0; g < 4; g++) {
        const unsigned long long* wr =
            (const unsigned long long*)(Whh + (size_t)(g * H_DIM + E) * H_DIM + 32 * w);
#pragma unroll
        for (int i = 0; i < 16; i++) wt[g][i] = wr[i];
    }

    // init
    for (int i = tid; i < 2 * H_DIM; i += 256) ((float*)hbuf)[i] = 0.0f;
    if (tid < 2 * CL) {
        asm volatile("mbarrier.init.shared.b64 [%0], %1;"
                     :: "r"(smem_bars + (uint32_t)tid * 8), "r"(1) : "memory");
    }
    __syncthreads();
    // pre-arm bars[w][1] for t=1 (consumer-side arm)
    if (e == 0) {
        asm volatile("mbarrier.arrive.expect_tx.shared.b64 _, [%0], %1;"
                     :: "r"(smem_bars + (uint32_t)(w * 2 + 1) * 8), "r"(128)
                     : "memory");
    }
    __syncthreads();
    asm volatile("barrier.cluster.arrive.aligned;" ::: "memory");
    asm volatile("barrier.cluster.wait.aligned;" ::: "memory");

    // push lanes (warp 0, all 32): lane l sends packets p0=l>>3 and p0+4
    // (local elems 4p..4p+3 and 4p+16..4p+19) to dest CTA (l&7).
    uint32_t dsth = 0, dstb = 0;
    if (w == 0) {
        uint32_t hoff = smem_h + (uint32_t)(rank * 32 + 4 * (e >> 3)) * 4;
        uint32_t boff = smem_bars + rank * 16;   // bars[rank][0]
        asm("mapa.shared::cluster.u32 %0, %1, %2;"
            : "=r"(dsth) : "r"(hoff), "r"(e & 7));
        asm("mapa.shared::cluster.u32 %0, %1, %2;"
            : "=r"(dstb) : "r"(boff), "r"(e & 7));
    }

    float c = 0.0f;
    float xn0 = 0.f, xn1 = 0.f, xn2 = 0.f, xn3 = 0.f;
    if (w == 0) {
        xn0 = g_xg[0 * H_DIM + E];
        xn1 = g_xg[1 * H_DIM + E];
        xn2 = g_xg[2 * H_DIM + E];
        xn3 = g_xg[3 * H_DIM + E];
    }

    const uint32_t mybar0 = smem_bars + (uint32_t)(w * 2) * 8;
    const uint32_t mybar1 = mybar0 + 8;

    for (int t = 0; t < T_STEPS; t++) {
        const uint32_t mybar = (t & 1) ? mybar1 : mybar0;
        // ---- wait ONLY this warp's source CTA, then re-arm for t+2 ----
        if (t > 0) mbar_wait(mybar, (uint32_t)(((t - 1) >> 1) & 1));
        if (e == 0) {
            asm volatile("mbarrier.arrive.expect_tx.shared.b64 _, [%0], %1;"
                         :: "r"(mybar), "r"(128) : "memory");
        }

        // ---- phase 1: partial dots over slice [32w,32w+32) ----
        const ulonglong2* hp =
            (const ulonglong2*)((const char*)hbuf + (t & 1) * (H_DIM * 4) + w * 128);
        unsigned long long hh[16];
#pragma unroll
        for (int i = 0; i < 8; i++) {
            ulonglong2 q = hp[i];
            hh[2 * i + 0] = q.x;
            hh[2 * i + 1] = q.y;
        }
        unsigned long long a0 = 0ull, a1 = 0ull, a2 = 0ull, a3 = 0ull;
#pragma unroll
        for (int j = 0; j < 16; j++) {
            ffma2(a0, wt[0][j], hh[j]);
            ffma2(a1, wt[1][j], hh[j]);
            ffma2(a2, wt[2][j], hh[j]);
            ffma2(a3, wt[3][j], hh[j]);
        }
        float4 p;
        p.x = lo32(a0) + hi32(a0);   // i
        p.y = lo32(a1) + hi32(a1);   // f
        p.z = lo32(a2) + hi32(a2);   // g
        p.w = lo32(a3) + hi32(a3);   // o
        *(float4*)&part[t & 1][w][e][0] = p;
        __syncthreads();

        // ---- phase 2: warp 0 reduces + MUFU activations + v4 push ----
        if (w == 0) {
            unsigned long long sA = 0ull, sB = 0ull;
#pragma unroll
            for (int ww = 0; ww < 8; ww++) {
                ulonglong2 v = *(const ulonglong2*)&part[t & 1][ww][e][0];
                fadd2(sA, v.x);   // (i,f)
                fadd2(sB, v.y);   // (g,o)
            }
            float iv = sigmoid_fast(lo32(sA) + xn0);
            float fv = sigmoid_fast(hi32(sA) + xn1);
            float gv = tanh_fast(lo32(sB) + xn2);
            float ov = sigmoid_fast(hi32(sB) + xn3);
            c = fv * c + iv * gv;
            float hv = ov * tanh_fast(c);

            if (t < T_STEPS - 1) {
                // gather packet elems via shfl; push 2 v4 packets per lane
                const uint32_t hvu = __float_as_uint(hv);
                const int p0 = 4 * (e >> 3);          // first packet base elem
                uint32_t q0 = __shfl_sync(0xFFFFFFFFu, hvu, p0 + 0);
                uint32_t q1 = __shfl_sync(0xFFFFFFFFu, hvu, p0 + 1);
                uint32_t q2 = __shfl_sync(0xFFFFFFFFu, hvu, p0 + 2);
                uint32_t q3 = __shfl_sync(0xFFFFFFFFu, hvu, p0 + 3);
                uint32_t r0 = __shfl_sync(0xFFFFFFFFu, hvu, p0 + 16);
                uint32_t r1 = __shfl_sync(0xFFFFFFFFu, hvu, p0 + 17);
                uint32_t r2 = __shfl_sync(0xFFFFFFFFu, hvu, p0 + 18);
                uint32_t r3 = __shfl_sync(0xFFFFFFFFu, hvu, p0 + 19);
                const uint32_t hoff = (uint32_t)((t + 1) & 1) * (H_DIM * 4);
                const uint32_t boff = (uint32_t)((t + 1) & 1) * 8;
                asm volatile(
                    "st.async.shared::cluster.mbarrier::complete_tx::bytes.v4.b32 "
                    "[%0], {%1,%2,%3,%4}, [%5];"
                    :: "r"(dsth + hoff), "r"(q0), "r"(q1), "r"(q2), "r"(q3),
                       "r"(dstb + boff)
                    : "memory");
                asm volatile(
                    "st.async.shared::cluster.mbarrier::complete_tx::bytes.v4.b32 "
                    "[%0], {%1,%2,%3,%4}, [%5];"
                    :: "r"(dsth + hoff + 64), "r"(r0), "r"(r1), "r"(r2), "r"(r3),
                       "r"(dstb + boff)
                    : "memory");
            }

            // off critical path: output + next xg prefetch
            out[(size_t)t * H_DIM + E] = hv;
            if (t == T_STEPS - 1) {
                out[(size_t)T_STEPS * H_DIM + E] = hv;
                out[(size_t)T_STEPS * H_DIM + H_DIM + E] = c;
            }
            {
                int tn = (t + 1 < T_STEPS) ? (t + 1) : t;
                const float* xr = g_xg + (size_t)tn * G_DIM + E;
                xn0 = xr[0]; xn1 = xr[256]; xn2 = xr[512]; xn3 = xr[768];
            }
        }
    }
}

// ---------------------------------------------------------------------------
extern "C" void kernel_launch(void* const* d_in, const int* in_sizes, int n_in,
                              void* d_out, int out_size) {
    const int* tokens = (const int*)d_in[0];
    const float* emb = (const float*)d_in[1];
    const float* Wih = (const float*)d_in[2];
    const float* Whh = (const float*)d_in[3];
    const float* bih = (const float*)d_in[4];
    const float* bhh = (const float*)d_in[5];
    float* out = (float*)d_out;

    dim3 gA(8, 64);
    xg_gemm<<<gA, 256>>>(tokens, emb, Wih, bih, bhh);
    lstm_scan<<<CL, 256>>>(Whh, out);
}